// round 16
// baseline (speedup 1.0000x reference)
#include <cuda_runtime.h>
#include <math.h>

typedef unsigned long long ull;

#define NBATCH 2048
#define NPAIR 1024

// ---------------- device scratch ----------------
__device__ __align__(16) ull g_wAt[2700];                            // composed 5x5 conv1*conv2, transposed [ci*25+k][oc], (w,w) pairs
__device__ float g_b2[18];
__device__ __align__(16) ull g_w34cp[11664];                         // composed conv3*conv4*avgpool 6x6 stride2, (w,w) pairs, [(ci*36+k)*18+oc]
__device__ float g_b34[18];
__device__ __align__(16) ull g_pool1p[(size_t)NPAIR * 18 * 30 * 30]; // pool1, sample-pair interleaved
__device__ __align__(16) float g_feat[(size_t)NBATCH * 3042];        // flattened features

// ---------------- packed f32x2 helpers ----------------
__device__ __forceinline__ void ffma2(ull& d, ull a, ull b) {
    asm("fma.rn.f32x2 %0, %1, %2, %0;" : "+l"(d) : "l"(a), "l"(b));
}
__device__ __forceinline__ ull pk2(float lo, float hi) {
    ull r;
    asm("mov.b64 %0, {%1, %2};" : "=l"(r) : "f"(lo), "f"(hi));
    return r;
}
__device__ __forceinline__ float2 upk2(ull v) {
    float2 r;
    asm("mov.b64 {%0, %1}, %2;" : "=f"(r.x), "=f"(r.y) : "l"(v));
    return r;
}

// ---------------- compose conv1*conv2 -> one 5x5 conv (transposed store) ----------------
__global__ void k_compose(const float* __restrict__ c1w, const float* __restrict__ c1b,
                          const float* __restrict__ c2w, const float* __restrict__ c2b) {
    int idx = blockIdx.x * blockDim.x + threadIdx.x;
    if (idx < 2700) {
        int o = idx / 150;
        int r = idx - o * 150;          // r = ci*25 + y*5 + x
        int ci = r / 25;
        int y = (r % 25) / 5;
        int x = r % 5;
        int ky_lo = y > 2 ? y - 2 : 0, ky_hi = y < 2 ? y : 2;
        int kx_lo = x > 2 ? x - 2 : 0, kx_hi = x < 2 ? x : 2;
        float s = 0.f;
        for (int m = 0; m < 18; m++)
            for (int ky = ky_lo; ky <= ky_hi; ky++)
                for (int kx = kx_lo; kx <= kx_hi; kx++)
                    s += c1w[((m * 6 + ci) * 3 + ky) * 3 + kx] *
                         c2w[((o * 18 + m) * 3 + (y - ky)) * 3 + (x - kx)];
        g_wAt[r * 18 + o] = pk2(s, s);
    } else if (idx < 2718) {
        int o = idx - 2700;
        float s = c2b[o];
        for (int m = 0; m < 18; m++) {
            float t = 0.f;
            for (int q = 0; q < 9; q++) t += c2w[(o * 18 + m) * 9 + q];
            s += c1b[m] * t;
        }
        g_b2[o] = s;
    }
}

// ---------------- compose conv3*conv4*avgpool -> 6x6 stride-2 conv (ull pairs) ----------------
__global__ void k_compose34(const float* __restrict__ c3w, const float* __restrict__ c3b,
                            const float* __restrict__ c4w, const float* __restrict__ c4b) {
    int idx = blockIdx.x * blockDim.x + threadIdx.x;
    if (idx < 11664) {
        int oc = idx % 18;
        int t = idx / 18;        // ci*36 + u*6 + v
        int ci = t / 36;
        int u = (t % 36) / 6;
        int v = t % 6;
        float s = 0.f;
        for (int m = 0; m < 18; m++) {
            for (int a = 0; a < 2; a++) {
                int y = u - a;
                if (y < 0 || y > 4) continue;
                for (int b = 0; b < 2; b++) {
                    int x = v - b;
                    if (x < 0 || x > 4) continue;
                    int ky_lo = y > 2 ? y - 2 : 0, ky_hi = y < 2 ? y : 2;
                    int kx_lo = x > 2 ? x - 2 : 0, kx_hi = x < 2 ? x : 2;
                    for (int ky = ky_lo; ky <= ky_hi; ky++)
                        for (int kx = kx_lo; kx <= kx_hi; kx++)
                            s += c4w[((oc * 18 + m) * 3 + ky) * 3 + kx] *
                                 c3w[((m * 18 + ci) * 3 + (y - ky)) * 3 + (x - kx)];
                }
            }
        }
        s *= 0.25f;
        g_w34cp[idx] = pk2(s, s);
    } else if (idx < 11682) {
        int oc = idx - 11664;
        float s = c4b[oc];
        for (int m = 0; m < 18; m++) {
            float t4 = 0.f;
            for (int q = 0; q < 9; q++) t4 += c4w[(oc * 18 + m) * 9 + q];
            s += c3b[m] * t4;
        }
        g_b34[oc] = s;
    }
}

// ---------------- convA (R14 verbatim): composed 5x5 (6->18) + maxpool2, 256 thr, 3 CTAs/SM ----------------
// grid (5 rowbands, 1024 pairs)
// smem: wAts 21600 | b2s 96 | inP 6*16*64 ull = 49152  => 70848
#define SMEM_A 70848

__global__ __launch_bounds__(256, 3) void k_convA(const float* __restrict__ states) {
    extern __shared__ char smA[];
    ull* wAts = (ull*)smA;              // [ci*25+k][oc]
    float* b2s = (float*)(smA + 21600);
    ull* inP = (ull*)(smA + 21696);
    const int tid = threadIdx.x;
    const int band = blockIdx.x;        // 0..4, 6 pooled rows each
    const int pair = blockIdx.y;
    const int ir0 = 12 * band;

    for (int i = tid; i < 2700; i += 256) wAts[i] = g_wAt[i];
    if (tid < 18) b2s[tid] = g_b2[tid];
    {
        const float4* s0 = (const float4*)(states) + (size_t)pair * 12288;
        for (int i = tid; i < 1536; i += 256) {
            int c4 = i & 15, r = (i >> 4) & 15, ci = i >> 8;
            int goff = (ci * 64 + ir0 + r) * 16 + c4;
            float4 a = s0[goff], b = s0[goff + 6144];
            ull* d = inP + (ci << 10) + (r << 6) + (c4 << 2);
            d[0] = pk2(a.x, b.x); d[1] = pk2(a.y, b.y);
            d[2] = pk2(a.z, b.z); d[3] = pk2(a.w, b.w);
        }
    }
    __syncthreads();

    // strips: pl(6) x blk(15) x oc(18) = 1620; oc fastest
    for (int t = tid; t < 1620; t += 256) {
        int oc = t % 18;
        int r2 = t / 18;
        int blk = r2 % 15;
        int pl = r2 / 15;
        int c0 = blk * 4;

        ull acc[2][4];
#pragma unroll
        for (int r = 0; r < 2; r++)
#pragma unroll
            for (int j = 0; j < 4; j++) acc[r][j] = 0ull;

#pragma unroll 1
        for (int ci = 0; ci < 6; ci++) {
            const ull* rb = inP + (ci << 10) + (pl << 7) + c0;
            const ull* wb = wAts + ci * 450 + oc;
            ull wn0 = 0, wn1 = 0, wn2 = 0, wn3 = 0, wn4 = 0;
            ull wp0 = 0, wp1 = 0, wp2 = 0, wp3 = 0, wp4 = 0;
#pragma unroll
            for (int iy = 0; iy < 6; iy++) {
                ull v[8];
                {
                    const ulonglong2* vp = (const ulonglong2*)(rb + (iy << 6));
#pragma unroll
                    for (int j = 0; j < 4; j++) { ulonglong2 q = vp[j]; v[2 * j] = q.x; v[2 * j + 1] = q.y; }
                }
                if (iy < 5) {
                    wn0 = wb[(iy * 5) * 18];
                    wn1 = wb[(iy * 5 + 1) * 18];
                    wn2 = wb[(iy * 5 + 2) * 18];
                    wn3 = wb[(iy * 5 + 3) * 18];
                    wn4 = wb[(iy * 5 + 4) * 18];
#pragma unroll
                    for (int j = 0; j < 4; j++) {
                        ffma2(acc[0][j], wn0, v[j]);
                        ffma2(acc[0][j], wn1, v[j + 1]);
                        ffma2(acc[0][j], wn2, v[j + 2]);
                        ffma2(acc[0][j], wn3, v[j + 3]);
                        ffma2(acc[0][j], wn4, v[j + 4]);
                    }
                }
                if (iy >= 1) {
#pragma unroll
                    for (int j = 0; j < 4; j++) {
                        ffma2(acc[1][j], wp0, v[j]);
                        ffma2(acc[1][j], wp1, v[j + 1]);
                        ffma2(acc[1][j], wp2, v[j + 2]);
                        ffma2(acc[1][j], wp3, v[j + 3]);
                        ffma2(acc[1][j], wp4, v[j + 4]);
                    }
                }
                wp0 = wn0; wp1 = wn1; wp2 = wn2; wp3 = wn3; wp4 = wn4;
            }
        }
        float bias = b2s[oc];
        int prow = band * 6 + pl;
        ull* op = g_pool1p + (((size_t)pair * 18 + oc) * 30 + prow) * 30 + blk * 2;
#pragma unroll
        for (int p = 0; p < 2; p++) {
            float2 a0 = upk2(acc[0][2 * p]), a1 = upk2(acc[0][2 * p + 1]);
            float2 b0 = upk2(acc[1][2 * p]), b1 = upk2(acc[1][2 * p + 1]);
            float mx = fmaxf(fmaxf(a0.x, a1.x), fmaxf(b0.x, b1.x)) + bias;
            float my = fmaxf(fmaxf(a0.y, a1.y), fmaxf(b0.y, b1.y)) + bias;
            op[p] = pk2(mx, my);
        }
    }
}

// ---------------- conv34c v4: 6x6 stride-2 conv (18->18), 30x30 pool1 -> 13x13 feat ----------------
// R13's measured-good 1-row strip structure + ull-pair weights (no pk2 in hot loop).
// grid (2 rowhalves, 1024 pairs), 512 thr, 2 CTAs/SM; 2 phases of 9 ci (weights + data co-phased).
// smem: wS 5832 ull (46656B) | b34 96 | dS <= 9*18*30 ull (38880B) => 85632
#define SMEM_C34 85632

__global__ __launch_bounds__(512, 2) void k_conv34c() {
    extern __shared__ char smE[];
    ull* wS = (ull*)smE;                   // [(cil*36 + k)*18 + oc]
    float* bS = (float*)(smE + 46656);
    ull* dS = (ull*)(smE + 46752);         // [cil][local row][col], stride 30, nr rows per ci
    const int tid = threadIdx.x;
    const int hf = blockIdx.x;             // 0: pr 0..6 (rows 0..17), 1: pr 7..12 (rows 14..29)
    const int pair = blockIdx.y;
    const int ir0 = hf ? 14 : 0;
    const int nr = hf ? 16 : 18;
    const int cistride = nr * 30;

    if (tid < 18) bS[tid] = g_b34[tid];

    const int oc = tid % 18;
    const int r2 = tid / 18;
    const int cq = r2 & 3;
    const int rl = r2 >> 2;                // local pooled row
    const int nstrip = (hf ? 6 : 7) * 72;
    const bool active = tid < nstrip;
    const int c0 = 6 * cq;

    ull acc[4];
#pragma unroll
    for (int j = 0; j < 4; j++) acc[j] = 0ull;

#pragma unroll 1
    for (int cp = 0; cp < 2; cp++) {
        __syncthreads();
        for (int i = tid; i < 5832; i += 512) wS[i] = g_w34cp[cp * 5832 + i];
        {
            const ull* src = g_pool1p + (size_t)pair * 16200 + cp * 8100;
            const int total = 9 * cistride;
            for (int e = tid; e < total; e += 512) {
                int cil = e / cistride;
                int rem = e - cil * cistride;
                int r = rem / 30, c = rem - r * 30;
                dS[e] = src[cil * 900 + (ir0 + r) * 30 + c];
            }
        }
        __syncthreads();

        if (active) {
#pragma unroll 1
            for (int cil = 0; cil < 9; cil++) {
                const ull* rb = dS + cil * cistride + 2 * rl * 30 + c0;
                const ull* wb = wS + cil * 648 + oc;
#pragma unroll
                for (int u = 0; u < 6; u++) {
                    ull v[12];
                    {
                        const ull* vp = rb + u * 30;
#pragma unroll
                        for (int j = 0; j < 12; j++) v[j] = vp[j];
                    }
#pragma unroll
                    for (int kx = 0; kx < 6; kx++) {
                        ull w = wb[(u * 6 + kx) * 18];
                        ffma2(acc[0], w, v[kx]);
                        ffma2(acc[1], w, v[kx + 2]);
                        ffma2(acc[2], w, v[kx + 4]);
                        ffma2(acc[3], w, v[kx + 6]);
                    }
                }
            }
        }
    }

    if (active) {
        float b = bS[oc];
        int pr = 7 * hf + rl;
        float* f0 = g_feat + (size_t)(2 * pair) * 3042 + (oc * 13 + pr) * 13 + 3 * cq;
        float* f1 = f0 + 3042;
        const int plo = cq ? 1 : 0;
#pragma unroll
        for (int pp = 0; pp < 4; pp++) {
            if (pp >= plo) {
                float2 vv = upk2(acc[pp]);
                f0[pp] = vv.x + b;
                f1[pp] = vv.y + b;
            }
        }
    }
}

// ---------------- MLP + expert routing + softmax, 8 samples/CTA (R4 verbatim) ----------------
#define SMEM_M ((8 * 3076 + 64 * 132 + 8 * 66 + 512 + 64) * 4)

__global__ __launch_bounds__(512, 1) void k_mlp(const float* __restrict__ scores, const float* __restrict__ times,
                                                const int* __restrict__ agents,
                                                const float* __restrict__ l1w, const float* __restrict__ l1b,
                                                const float* __restrict__ l2w, const float* __restrict__ l2b,
                                                const float* __restrict__ agw, const float* __restrict__ agb,
                                                float* __restrict__ out) {
    extern __shared__ float smM[];
    float* featS = smM;
    float* wT = featS + 8 * 3076;
    float* h1S = wT + 64 * 132;
    float* h2S = h1S + 8 * 66;
    float* logS = h2S + 512;
    const int tid = threadIdx.x;
    const int sb = blockIdx.x * 8;

    for (int i = tid; i < 8 * 1521; i += 512) {
        int s = i / 1521;
        int r = i - s * 1521;
        ((float2*)(featS + s * 3076))[r] = ((const float2*)(g_feat + (size_t)(sb + s) * 3042))[r];
    }
    if (tid < 8) {
        featS[tid * 3076 + 3042] = scores[sb + tid];
        featS[tid * 3076 + 3043] = times[sb + tid];
    }
    if (tid >= 32 && tid < 288) {
        int j = tid - 32;
        featS[(j >> 5) * 3076 + 3044 + (j & 31)] = 0.f;
    }
    __syncthreads();

    const int s = tid & 7, o = tid >> 3;
    ull f0a = 0, f1a = 0, f2a = 0, f3a = 0;
#pragma unroll 1
    for (int kt = 0; kt < 24; kt++) {
        int k0 = kt << 7;
        for (int i = tid; i < 8192; i += 512) {
            int oo = i >> 7, kk = i & 127;
            int k = k0 + kk;
            wT[oo * 132 + kk] = (k < 3044) ? l1w[oo * 3044 + k] : 0.f;
        }
        __syncthreads();
        const ull* fr = (const ull*)(featS + s * 3076 + k0);
        const ull* wr = (const ull*)(wT + o * 132);
#pragma unroll
        for (int kk = 0; kk < 64; kk += 4) {
            ffma2(f0a, fr[kk], wr[kk]);
            ffma2(f1a, fr[kk + 1], wr[kk + 1]);
            ffma2(f2a, fr[kk + 2], wr[kk + 2]);
            ffma2(f3a, fr[kk + 3], wr[kk + 3]);
        }
        __syncthreads();
    }
    {
        float2 a = upk2(f0a), b = upk2(f1a), c = upk2(f2a), d = upk2(f3a);
        float acc = (a.x + a.y) + (b.x + b.y) + (c.x + c.y) + (d.x + d.y);
        h1S[s * 66 + o] = tanhf(acc + l1b[o]);
    }
    __syncthreads();
    {
        const ull* hr = (const ull*)(h1S + s * 66);
        const ull* w2 = (const ull*)(l2w + o * 64);
        ull a0 = 0, a1 = 0;
#pragma unroll
        for (int kk = 0; kk < 32; kk += 2) {
            ffma2(a0, hr[kk], w2[kk]);
            ffma2(a1, hr[kk + 1], w2[kk + 1]);
        }
        float2 a = upk2(a0), b = upk2(a1);
        h2S[s * 64 + o] = tanhf(a.x + a.y + b.x + b.y + l2b[o]);
    }
    __syncthreads();
    if (tid < 40) {
        int ss = tid / 5, oo = tid - ss * 5;
        int ag = agents[sb + ss];
        const float* W = agw + (ag * 5 + oo) * 64;
        const float* h = h2S + ss * 64;
        float a = agb[ag * 5 + oo];
#pragma unroll
        for (int k = 0; k < 64; k++) a += W[k] * h[k];
        logS[ss * 8 + oo] = a;
    }
    __syncthreads();
    if (tid < 8) {
        float m = -1e30f;
        for (int i = 0; i < 5; i++) m = fmaxf(m, logS[tid * 8 + i]);
        float e[5], sum = 0.f;
        for (int i = 0; i < 5; i++) { e[i] = expf(logS[tid * 8 + i] - m); sum += e[i]; }
        float inv = 1.f / sum;
        for (int i = 0; i < 5; i++) out[(sb + tid) * 5 + i] = e[i] * inv;
    }
}

// ---------------- launch ----------------
extern "C" void kernel_launch(void* const* d_in, const int* in_sizes, int n_in,
                              void* d_out, int out_size) {
    const float* states = (const float*)d_in[0];
    const float* scores = (const float*)d_in[1];
    const float* times  = (const float*)d_in[2];
    const int*   agents = (const int*)d_in[3];
    const float* c1w = (const float*)d_in[4];
    const float* c1b = (const float*)d_in[5];
    const float* c2w = (const float*)d_in[6];
    const float* c2b = (const float*)d_in[7];
    const float* c3w = (const float*)d_in[8];
    const float* c3b = (const float*)d_in[9];
    const float* c4w = (const float*)d_in[10];
    const float* c4b = (const float*)d_in[11];
    const float* l1w = (const float*)d_in[12];
    const float* l1b = (const float*)d_in[13];
    const float* l2w = (const float*)d_in[14];
    const float* l2b = (const float*)d_in[15];
    const float* agw = (const float*)d_in[16];
    const float* agb = (const float*)d_in[17];
    float* out = (float*)d_out;

    cudaFuncSetAttribute(k_convA, cudaFuncAttributeMaxDynamicSharedMemorySize, SMEM_A);
    cudaFuncSetAttribute(k_conv34c, cudaFuncAttributeMaxDynamicSharedMemorySize, SMEM_C34);
    cudaFuncSetAttribute(k_mlp, cudaFuncAttributeMaxDynamicSharedMemorySize, SMEM_M);

    k_compose<<<3, 1024>>>(c1w, c1b, c2w, c2b);
    k_compose34<<<23, 512>>>(c3w, c3b, c4w, c4b);
    k_convA<<<dim3(5, 1024), 256, SMEM_A>>>(states);
    k_conv34c<<<dim3(2, 1024), 512, SMEM_C34>>>();
    k_mlp<<<256, 512, SMEM_M>>>(scores, times, agents, l1w, l1b, l2w, l2b, agw, agb, out);
}

// round 17
// speedup vs baseline: 1.2160x; 1.2160x over previous
#include <cuda_runtime.h>
#include <math.h>

typedef unsigned long long ull;

#define NBATCH 2048
#define NPAIR 1024

// ---------------- device scratch ----------------
__device__ __align__(16) float g_wAf[2700];                          // composed 5x5 conv1*conv2, transposed [(ci*25+k)*18+oc], floats
__device__ float g_b2[18];
__device__ __align__(16) float g_w34c[11664];                        // composed conv3*conv4*avgpool 6x6 stride2, floats, [(ci*36+k)*18+oc]
__device__ float g_b34[18];
__device__ __align__(16) ull g_pool1p[(size_t)NPAIR * 18 * 30 * 30]; // pool1, sample-pair interleaved
__device__ __align__(16) float g_feat[(size_t)NBATCH * 3042];        // flattened features

// ---------------- packed f32x2 helpers ----------------
__device__ __forceinline__ void ffma2(ull& d, ull a, ull b) {
    asm("fma.rn.f32x2 %0, %1, %2, %0;" : "+l"(d) : "l"(a), "l"(b));
}
__device__ __forceinline__ ull pk2(float lo, float hi) {
    ull r;
    asm("mov.b64 %0, {%1, %2};" : "=l"(r) : "f"(lo), "f"(hi));
    return r;
}
__device__ __forceinline__ float2 upk2(ull v) {
    float2 r;
    asm("mov.b64 {%0, %1}, %2;" : "=f"(r.x), "=f"(r.y) : "l"(v));
    return r;
}

// ---------------- compose conv1*conv2 -> one 5x5 conv (transposed float store) ----------------
__global__ void k_compose(const float* __restrict__ c1w, const float* __restrict__ c1b,
                          const float* __restrict__ c2w, const float* __restrict__ c2b) {
    int idx = blockIdx.x * blockDim.x + threadIdx.x;
    if (idx < 2700) {
        int o = idx / 150;
        int r = idx - o * 150;          // r = ci*25 + y*5 + x
        int ci = r / 25;
        int y = (r % 25) / 5;
        int x = r % 5;
        int ky_lo = y > 2 ? y - 2 : 0, ky_hi = y < 2 ? y : 2;
        int kx_lo = x > 2 ? x - 2 : 0, kx_hi = x < 2 ? x : 2;
        float s = 0.f;
        for (int m = 0; m < 18; m++)
            for (int ky = ky_lo; ky <= ky_hi; ky++)
                for (int kx = kx_lo; kx <= kx_hi; kx++)
                    s += c1w[((m * 6 + ci) * 3 + ky) * 3 + kx] *
                         c2w[((o * 18 + m) * 3 + (y - ky)) * 3 + (x - kx)];
        g_wAf[r * 18 + o] = s;
    } else if (idx < 2718) {
        int o = idx - 2700;
        float s = c2b[o];
        for (int m = 0; m < 18; m++) {
            float t = 0.f;
            for (int q = 0; q < 9; q++) t += c2w[(o * 18 + m) * 9 + q];
            s += c1b[m] * t;
        }
        g_b2[o] = s;
    }
}

// ---------------- compose conv3*conv4*avgpool -> 6x6 stride-2 conv (floats) ----------------
__global__ void k_compose34(const float* __restrict__ c3w, const float* __restrict__ c3b,
                            const float* __restrict__ c4w, const float* __restrict__ c4b) {
    int idx = blockIdx.x * blockDim.x + threadIdx.x;
    if (idx < 11664) {
        int oc = idx % 18;
        int t = idx / 18;        // ci*36 + u*6 + v
        int ci = t / 36;
        int u = (t % 36) / 6;
        int v = t % 6;
        float s = 0.f;
        for (int m = 0; m < 18; m++) {
            for (int a = 0; a < 2; a++) {
                int y = u - a;
                if (y < 0 || y > 4) continue;
                for (int b = 0; b < 2; b++) {
                    int x = v - b;
                    if (x < 0 || x > 4) continue;
                    int ky_lo = y > 2 ? y - 2 : 0, ky_hi = y < 2 ? y : 2;
                    int kx_lo = x > 2 ? x - 2 : 0, kx_hi = x < 2 ? x : 2;
                    for (int ky = ky_lo; ky <= ky_hi; ky++)
                        for (int kx = kx_lo; kx <= kx_hi; kx++)
                            s += c4w[((oc * 18 + m) * 3 + ky) * 3 + kx] *
                                 c3w[((m * 18 + ci) * 3 + (y - ky)) * 3 + (x - kx)];
                }
            }
        }
        g_w34c[idx] = 0.25f * s;
    } else if (idx < 11682) {
        int oc = idx - 11664;
        float s = c4b[oc];
        for (int m = 0; m < 18; m++) {
            float t4 = 0.f;
            for (int q = 0; q < 9; q++) t4 += c4w[(oc * 18 + m) * 9 + q];
            s += c3b[m] * t4;
        }
        g_b34[oc] = s;
    }
}

// ---------------- convA v3: composed 5x5 (6->18) + maxpool2 ----------------
// 256 thr, 3 CTAs/SM; scalar LDS.64 data loads (1 wf) + float weights + pk2 at load.
// grid (5 rowbands, 1024 pairs)
// smem: wAfs 10800 | b2s 96 | inP 6*16*64 ull = 49152  => 60048
#define SMEM_A 60048

__global__ __launch_bounds__(256, 3) void k_convA(const float* __restrict__ states) {
    extern __shared__ char smA[];
    float* wAfs = (float*)smA;          // [(ci*25+k)*18+oc]
    float* b2s = (float*)(smA + 10800);
    ull* inP = (ull*)(smA + 10896);
    const int tid = threadIdx.x;
    const int band = blockIdx.x;        // 0..4, 6 pooled rows each
    const int pair = blockIdx.y;
    const int ir0 = 12 * band;

    for (int i = tid; i < 2700; i += 256) wAfs[i] = g_wAf[i];
    if (tid < 18) b2s[tid] = g_b2[tid];
    {
        const float4* s0 = (const float4*)(states) + (size_t)pair * 12288;
        for (int i = tid; i < 1536; i += 256) {
            int c4 = i & 15, r = (i >> 4) & 15, ci = i >> 8;
            int goff = (ci * 64 + ir0 + r) * 16 + c4;
            float4 a = s0[goff], b = s0[goff + 6144];
            ull* d = inP + (ci << 10) + (r << 6) + (c4 << 2);
            d[0] = pk2(a.x, b.x); d[1] = pk2(a.y, b.y);
            d[2] = pk2(a.z, b.z); d[3] = pk2(a.w, b.w);
        }
    }
    __syncthreads();

    // strips: pl(6) x blk(15) x oc(18) = 1620; oc fastest
    for (int t = tid; t < 1620; t += 256) {
        int oc = t % 18;
        int r2 = t / 18;
        int blk = r2 % 15;
        int pl = r2 / 15;
        int c0 = blk * 4;

        ull acc[2][4];
#pragma unroll
        for (int r = 0; r < 2; r++)
#pragma unroll
            for (int j = 0; j < 4; j++) acc[r][j] = 0ull;

#pragma unroll 1
        for (int ci = 0; ci < 6; ci++) {
            const ull* rb = inP + (ci << 10) + (pl << 7) + c0;
            const float* wb = wAfs + ci * 450 + oc;   // (ci*25)*18 + oc
            ull wn0 = 0, wn1 = 0, wn2 = 0, wn3 = 0, wn4 = 0;
            ull wp0 = 0, wp1 = 0, wp2 = 0, wp3 = 0, wp4 = 0;
#pragma unroll
            for (int iy = 0; iy < 6; iy++) {
                ull v[8];
                {
                    const ull* vp = rb + (iy << 6);
#pragma unroll
                    for (int j = 0; j < 8; j++) v[j] = vp[j];
                }
                if (iy < 5) {
                    float f0 = wb[(iy * 5) * 18];
                    float f1 = wb[(iy * 5 + 1) * 18];
                    float f2 = wb[(iy * 5 + 2) * 18];
                    float f3 = wb[(iy * 5 + 3) * 18];
                    float f4 = wb[(iy * 5 + 4) * 18];
                    wn0 = pk2(f0, f0); wn1 = pk2(f1, f1); wn2 = pk2(f2, f2);
                    wn3 = pk2(f3, f3); wn4 = pk2(f4, f4);
#pragma unroll
                    for (int j = 0; j < 4; j++) {
                        ffma2(acc[0][j], wn0, v[j]);
                        ffma2(acc[0][j], wn1, v[j + 1]);
                        ffma2(acc[0][j], wn2, v[j + 2]);
                        ffma2(acc[0][j], wn3, v[j + 3]);
                        ffma2(acc[0][j], wn4, v[j + 4]);
                    }
                }
                if (iy >= 1) {
#pragma unroll
                    for (int j = 0; j < 4; j++) {
                        ffma2(acc[1][j], wp0, v[j]);
                        ffma2(acc[1][j], wp1, v[j + 1]);
                        ffma2(acc[1][j], wp2, v[j + 2]);
                        ffma2(acc[1][j], wp3, v[j + 3]);
                        ffma2(acc[1][j], wp4, v[j + 4]);
                    }
                }
                wp0 = wn0; wp1 = wn1; wp2 = wn2; wp3 = wn3; wp4 = wn4;
            }
        }
        float bias = b2s[oc];
        int prow = band * 6 + pl;
        ull* op = g_pool1p + (((size_t)pair * 18 + oc) * 30 + prow) * 30 + blk * 2;
#pragma unroll
        for (int p = 0; p < 2; p++) {
            float2 a0 = upk2(acc[0][2 * p]), a1 = upk2(acc[0][2 * p + 1]);
            float2 b0 = upk2(acc[1][2 * p]), b1 = upk2(acc[1][2 * p + 1]);
            float mx = fmaxf(fmaxf(a0.x, a1.x), fmaxf(b0.x, b1.x)) + bias;
            float my = fmaxf(fmaxf(a0.y, a1.y), fmaxf(b0.y, b1.y)) + bias;
            op[p] = pk2(mx, my);
        }
    }
}

// ---------------- conv34c (R13 verbatim, 269us measured): 6x6 stride-2 conv, 30x30 -> 13x13 ----------------
// grid (2 rowhalves, 1024 pairs), 512 thr, 2 CTAs/SM
// smem: wS 5832 floats (23328B, one 9-ci phase) | b34 96 | dS 18*18*30 ull (77760B) => 101184
#define SMEM_C34 101184

__global__ __launch_bounds__(512, 2) void k_conv34c() {
    extern __shared__ char smE[];
    float* wS = (float*)smE;               // [(ci_l*36 + k)*18 + oc]
    float* bS = (float*)(smE + 23328);
    ull* dS = (ull*)(smE + 23424);         // [ci][row][col], stride 30
    const int tid = threadIdx.x;
    const int hf = blockIdx.x;             // 0: pr 0..6 (rows 0..17), 1: pr 7..12 (rows 14..29)
    const int pair = blockIdx.y;
    const int ir0 = hf ? 14 : 0;
    const int nr = hf ? 16 : 18;

    if (tid < 18) bS[tid] = g_b34[tid];
    {
        const ull* src = g_pool1p + (size_t)pair * 16200;
        int per_ci = nr * 30;
        int total = 18 * per_ci;
        for (int e = tid; e < total; e += 512) {
            int ci = e / per_ci;
            int rem = e - ci * per_ci;
            int r = rem / 30, c = rem - r * 30;
            dS[ci * 540 + r * 30 + c] = src[(ci * 30 + ir0 + r) * 30 + c];
        }
    }
    for (int i = tid; i < 5832; i += 512) wS[i] = g_w34c[i];
    __syncthreads();

    const int nstrip = (hf ? 6 : 7) * 4 * 18;
    int oc = 0, cq = 0, pr_l = 0;
    if (tid < nstrip) {
        oc = tid % 18;
        int r2 = tid / 18;
        cq = r2 % 4;
        pr_l = r2 / 4;
    }
    const int c0 = 6 * cq;

    ull acc[4];
#pragma unroll
    for (int j = 0; j < 4; j++) acc[j] = 0ull;

#pragma unroll 1
    for (int cp = 0; cp < 2; cp++) {
        if (cp == 1) {
            __syncthreads();
            for (int i = tid; i < 5832; i += 512) wS[i] = g_w34c[5832 + i];
            __syncthreads();
        }
        if (tid < nstrip) {
#pragma unroll 1
            for (int cil = 0; cil < 9; cil++) {
                int ci = cp * 9 + cil;
                const ull* rb = dS + ci * 540 + (2 * pr_l) * 30 + c0;
                const float* wb = wS + cil * 648 + oc;
#pragma unroll
                for (int u = 0; u < 6; u++) {
                    ull v[12];
                    {
                        const ull* vp = rb + u * 30;
#pragma unroll
                        for (int j = 0; j < 12; j++) v[j] = vp[j];
                    }
#pragma unroll
                    for (int kx = 0; kx < 6; kx++) {
                        float wf = wb[(u * 6 + kx) * 18];
                        ull w = pk2(wf, wf);
                        ffma2(acc[0], w, v[kx]);
                        ffma2(acc[1], w, v[kx + 2]);
                        ffma2(acc[2], w, v[kx + 4]);
                        ffma2(acc[3], w, v[kx + 6]);
                    }
                }
            }
        }
    }

    if (tid < nstrip) {
        float b = bS[oc];
        int pr = 7 * hf + pr_l;
        float* f0 = g_feat + (size_t)(2 * pair) * 3042 + (oc * 13 + pr) * 13 + 3 * cq;
        float* f1 = f0 + 3042;
        int plo = cq ? 1 : 0;
#pragma unroll
        for (int pp = 0; pp < 4; pp++) {
            if (pp >= plo) {
                float2 vv = upk2(acc[pp]);
                f0[pp] = vv.x + b;
                f1[pp] = vv.y + b;
            }
        }
    }
}

// ---------------- MLP + expert routing + softmax, 8 samples/CTA (R4 verbatim) ----------------
#define SMEM_M ((8 * 3076 + 64 * 132 + 8 * 66 + 512 + 64) * 4)

__global__ __launch_bounds__(512, 1) void k_mlp(const float* __restrict__ scores, const float* __restrict__ times,
                                                const int* __restrict__ agents,
                                                const float* __restrict__ l1w, const float* __restrict__ l1b,
                                                const float* __restrict__ l2w, const float* __restrict__ l2b,
                                                const float* __restrict__ agw, const float* __restrict__ agb,
                                                float* __restrict__ out) {
    extern __shared__ float smM[];
    float* featS = smM;
    float* wT = featS + 8 * 3076;
    float* h1S = wT + 64 * 132;
    float* h2S = h1S + 8 * 66;
    float* logS = h2S + 512;
    const int tid = threadIdx.x;
    const int sb = blockIdx.x * 8;

    for (int i = tid; i < 8 * 1521; i += 512) {
        int s = i / 1521;
        int r = i - s * 1521;
        ((float2*)(featS + s * 3076))[r] = ((const float2*)(g_feat + (size_t)(sb + s) * 3042))[r];
    }
    if (tid < 8) {
        featS[tid * 3076 + 3042] = scores[sb + tid];
        featS[tid * 3076 + 3043] = times[sb + tid];
    }
    if (tid >= 32 && tid < 288) {
        int j = tid - 32;
        featS[(j >> 5) * 3076 + 3044 + (j & 31)] = 0.f;
    }
    __syncthreads();

    const int s = tid & 7, o = tid >> 3;
    ull f0a = 0, f1a = 0, f2a = 0, f3a = 0;
#pragma unroll 1
    for (int kt = 0; kt < 24; kt++) {
        int k0 = kt << 7;
        for (int i = tid; i < 8192; i += 512) {
            int oo = i >> 7, kk = i & 127;
            int k = k0 + kk;
            wT[oo * 132 + kk] = (k < 3044) ? l1w[oo * 3044 + k] : 0.f;
        }
        __syncthreads();
        const ull* fr = (const ull*)(featS + s * 3076 + k0);
        const ull* wr = (const ull*)(wT + o * 132);
#pragma unroll
        for (int kk = 0; kk < 64; kk += 4) {
            ffma2(f0a, fr[kk], wr[kk]);
            ffma2(f1a, fr[kk + 1], wr[kk + 1]);
            ffma2(f2a, fr[kk + 2], wr[kk + 2]);
            ffma2(f3a, fr[kk + 3], wr[kk + 3]);
        }
        __syncthreads();
    }
    {
        float2 a = upk2(f0a), b = upk2(f1a), c = upk2(f2a), d = upk2(f3a);
        float acc = (a.x + a.y) + (b.x + b.y) + (c.x + c.y) + (d.x + d.y);
        h1S[s * 66 + o] = tanhf(acc + l1b[o]);
    }
    __syncthreads();
    {
        const ull* hr = (const ull*)(h1S + s * 66);
        const ull* w2 = (const ull*)(l2w + o * 64);
        ull a0 = 0, a1 = 0;
#pragma unroll
        for (int kk = 0; kk < 32; kk += 2) {
            ffma2(a0, hr[kk], w2[kk]);
            ffma2(a1, hr[kk + 1], w2[kk + 1]);
        }
        float2 a = upk2(a0), b = upk2(a1);
        h2S[s * 64 + o] = tanhf(a.x + a.y + b.x + b.y + l2b[o]);
    }
    __syncthreads();
    if (tid < 40) {
        int ss = tid / 5, oo = tid - ss * 5;
        int ag = agents[sb + ss];
        const float* W = agw + (ag * 5 + oo) * 64;
        const float* h = h2S + ss * 64;
        float a = agb[ag * 5 + oo];
#pragma unroll
        for (int k = 0; k < 64; k++) a += W[k] * h[k];
        logS[ss * 8 + oo] = a;
    }
    __syncthreads();
    if (tid < 8) {
        float m = -1e30f;
        for (int i = 0; i < 5; i++) m = fmaxf(m, logS[tid * 8 + i]);
        float e[5], sum = 0.f;
        for (int i = 0; i < 5; i++) { e[i] = expf(logS[tid * 8 + i] - m); sum += e[i]; }
        float inv = 1.f / sum;
        for (int i = 0; i < 5; i++) out[(sb + tid) * 5 + i] = e[i] * inv;
    }
}

// ---------------- launch ----------------
extern "C" void kernel_launch(void* const* d_in, const int* in_sizes, int n_in,
                              void* d_out, int out_size) {
    const float* states = (const float*)d_in[0];
    const float* scores = (const float*)d_in[1];
    const float* times  = (const float*)d_in[2];
    const int*   agents = (const int*)d_in[3];
    const float* c1w = (const float*)d_in[4];
    const float* c1b = (const float*)d_in[5];
    const float* c2w = (const float*)d_in[6];
    const float* c2b = (const float*)d_in[7];
    const float* c3w = (const float*)d_in[8];
    const float* c3b = (const float*)d_in[9];
    const float* c4w = (const float*)d_in[10];
    const float* c4b = (const float*)d_in[11];
    const float* l1w = (const float*)d_in[12];
    const float* l1b = (const float*)d_in[13];
    const float* l2w = (const float*)d_in[14];
    const float* l2b = (const float*)d_in[15];
    const float* agw = (const float*)d_in[16];
    const float* agb = (const float*)d_in[17];
    float* out = (float*)d_out;

    cudaFuncSetAttribute(k_convA, cudaFuncAttributeMaxDynamicSharedMemorySize, SMEM_A);
    cudaFuncSetAttribute(k_conv34c, cudaFuncAttributeMaxDynamicSharedMemorySize, SMEM_C34);
    cudaFuncSetAttribute(k_mlp, cudaFuncAttributeMaxDynamicSharedMemorySize, SMEM_M);

    k_compose<<<3, 1024>>>(c1w, c1b, c2w, c2b);
    k_compose34<<<23, 512>>>(c3w, c3b, c4w, c4b);
    k_convA<<<dim3(5, 1024), 256, SMEM_A>>>(states);
    k_conv34c<<<dim3(2, 1024), 512, SMEM_C34>>>();
    k_mlp<<<256, 512, SMEM_M>>>(scores, times, agents, l1w, l1b, l2w, l2b, agw, agb, out);
}